// round 5
// baseline (speedup 1.0000x reference)
#include <cuda_runtime.h>
#include <cuda_bf16.h>
#include <cstdint>

// Problem constants (from reference):
//   NUM_BLOCKS=1024, BLOCK_SIZE=128, NUM_TOKENS=8192, NUM_KV_HEADS=8, HEAD_SIZE=128
// Row per (block,offset) slot = 8*128 = 1024 fp32 = 4096 B = 256 float4.

static constexpr long long INPUT_ELEMS = 8192LL * 8 * 128;  // 8,388,608
static constexpr int NUM_TOKENS = 8192;
static constexpr int NUM_ROWS = 1024 * 128;   // 131072 slot rows in the cache
static constexpr int ROW_F4 = 256;            // float4 per row
static constexpr int ROWS_PER_CTA = 4;

// Inverse slot map: map[row] = token_id + 1, or 0 if no token scatters to row.
// Statically zero-initialized; the main pass clears the entries it consumed,
// so every graph replay starts from an all-zero map (no memset node needed).
__device__ int g_slot_map[NUM_ROWS];

__global__ void fill_map_kernel(const int* __restrict__ block_indices,
                                const int* __restrict__ block_offset) {
    const int t = blockIdx.x * blockDim.x + threadIdx.x;
    if (t < NUM_TOKENS) {
        const int slot = block_indices[t] * 128 + block_offset[t];
        g_slot_map[slot] = t + 1;
    }
    // PDL: release the dependent (main) grid as soon as the map is written.
    cudaTriggerProgrammaticLaunchCompletion();
}

// One pass over the whole output. Each CTA: 4 rows x 4 KB = 16 KB.
// All 4 loads issued before any store for MLP. Streaming hints: every byte
// is touched exactly once, so evict-first in L2.
__global__ void __launch_bounds__(256) fused_scatter_copy_kernel(
    const float4* __restrict__ in,
    const float4* __restrict__ cache,
    float4* __restrict__ out) {
    // PDL: CTAs are already resident while fill_map runs; wait for its writes.
    cudaGridDependencySynchronize();

    const int row0 = blockIdx.x * ROWS_PER_CTA;
    const int lane = threadIdx.x;  // 0..255

    const float4* src[ROWS_PER_CTA];
    int tok[ROWS_PER_CTA];
    float4 v[ROWS_PER_CTA];

#pragma unroll
    for (int r = 0; r < ROWS_PER_CTA; r++) {
        const int row = row0 + r;
        tok[r] = g_slot_map[row];  // broadcast load (same addr across CTA)
        src[r] = (tok[r] != 0) ? (in + (long long)(tok[r] - 1) * ROW_F4)
                               : (cache + (long long)row * ROW_F4);
    }
#pragma unroll
    for (int r = 0; r < ROWS_PER_CTA; r++) v[r] = __ldcs(&src[r][lane]);
#pragma unroll
    for (int r = 0; r < ROWS_PER_CTA; r++)
        __stcs(&out[(long long)(row0 + r) * ROW_F4 + lane], v[r]);

    // Self-clean the map for the next graph replay (32 KB total across grid).
    if (lane == 0) {
#pragma unroll
        for (int r = 0; r < ROWS_PER_CTA; r++)
            if (tok[r] != 0) g_slot_map[row0 + r] = 0;
    }
}

extern "C" void kernel_launch(void* const* d_in, const int* in_sizes, int n_in,
                              void* d_out, int out_size) {
    const float* input = nullptr;
    const float* cache = nullptr;
    const int* block_indices = nullptr;
    const int* block_offset = nullptr;

    // Identify inputs by element count (robust to scalar args being present or not).
    for (int i = 0; i < n_in; i++) {
        const long long sz = (long long)in_sizes[i];
        if (sz == INPUT_ELEMS && input == nullptr) {
            input = (const float*)d_in[i];
        } else if (sz == (long long)out_size && cache == nullptr) {
            cache = (const float*)d_in[i];
        } else if (sz == NUM_TOKENS) {
            if (block_indices == nullptr) block_indices = (const int*)d_in[i];
            else if (block_offset == nullptr) block_offset = (const int*)d_in[i];
        }
    }

    float* out = (float*)d_out;

    // 1) Build inverse map: map[slot] = token + 1 (map arrives all-zero).
    fill_map_kernel<<<(NUM_TOKENS + 255) / 256, 256, 0, 0>>>(block_indices, block_offset);

    // 2) Single fused pass; launched with programmatic stream serialization so
    //    it overlaps fill_map's execution and the launch gap, then syncs on the
    //    map via cudaGridDependencySynchronize() inside the kernel.
    cudaLaunchConfig_t cfg = {};
    cfg.gridDim = dim3(NUM_ROWS / ROWS_PER_CTA, 1, 1);
    cfg.blockDim = dim3(256, 1, 1);
    cfg.dynamicSmemBytes = 0;
    cfg.stream = 0;
    cudaLaunchAttribute attr[1];
    attr[0].id = cudaLaunchAttributeProgrammaticStreamSerialization;
    attr[0].val.programmaticStreamSerializationAllowed = 1;
    cfg.attrs = attr;
    cfg.numAttrs = 1;
    cudaLaunchKernelEx(&cfg, fused_scatter_copy_kernel,
                       (const float4*)input, (const float4*)cache, (float4*)out);
}